// round 3
// baseline (speedup 1.0000x reference)
#include <cuda_runtime.h>

#define NN   100000
#define MAXE 1600000

// ---------------- device scratch (static; no allocations) ----------------
__device__ __align__(16) float g_t[(size_t)NN * 128];   // transformed feats
__device__ __align__(16) float g_h[(size_t)NN * 128];   // layer outputs
__device__ float g_dinv[NN];
__device__ float g_as[NN];
__device__ float g_bs[NN];
__device__ int   g_cnt[NN];
__device__ int   g_rowstart[NN + 1];
__device__ int   g_fill[NN];
__device__ int   g_bsum[256];
__device__ int   g_csr[MAXE];   // src node per CSR slot (grouped by dst)
__device__ int   g_is64;        // 1 if edge_index buffer is int64-laid-out

// ---------------- edge index accessors (dtype-agnostic) ----------------
__device__ __forceinline__ int esrc(const int* __restrict__ ei, int e) {
    return g_is64 ? ei[2 * e] : ei[e];
}
__device__ __forceinline__ int edst(const int* __restrict__ ei, int e, int E) {
    return g_is64 ? ei[2 * (E + e)] : ei[E + e];
}

// Probe layout: if int64 little-endian, every odd int32 slot (high word of a
// small nonneg id) is 0. If int32, odd slots are real ids (~0 prob all zero).
__global__ void k_detect(const int* __restrict__ ei) {
    int odd_nonzero = 0;
    for (int i = threadIdx.x; i < 256; i += 32)
        if (ei[2 * i + 1] != 0) odd_nonzero = 1;
    unsigned m = __ballot_sync(0xFFFFFFFFu, odd_nonzero);
    if (threadIdx.x == 0) g_is64 = (m == 0) ? 1 : 0;
}

// ---------------- graph preprocessing ----------------
__global__ void k_zero_cnt() {
    int i = blockIdx.x * blockDim.x + threadIdx.x;
    if (i < NN) g_cnt[i] = 0;
}

__global__ void k_hist(const int* __restrict__ ei, int E) {
    int e = blockIdx.x * blockDim.x + threadIdx.x;
    if (e < E) atomicAdd(&g_cnt[edst(ei, e, E)], 1);
}

// inclusive scan per 1024-chunk; writes rowstart[i+1], block sums to g_bsum
__global__ void k_scan1() {
    __shared__ int sh[1024];
    int i = blockIdx.x * 1024 + threadIdx.x;
    int v = (i < NN) ? g_cnt[i] : 0;
    sh[threadIdx.x] = v;
    __syncthreads();
    for (int off = 1; off < 1024; off <<= 1) {
        int t = (threadIdx.x >= off) ? sh[threadIdx.x - off] : 0;
        __syncthreads();
        sh[threadIdx.x] += t;
        __syncthreads();
    }
    if (i < NN) g_rowstart[i + 1] = sh[threadIdx.x];
    if (threadIdx.x == 1023) g_bsum[blockIdx.x] = sh[1023];
    if (i == 0) g_rowstart[0] = 0;
}

__global__ void k_scan2(int nblocks) {
    if (threadIdx.x == 0 && blockIdx.x == 0) {
        int acc = 0;
        for (int b = 0; b < nblocks; b++) {
            int v = g_bsum[b];
            g_bsum[b] = acc;
            acc += v;
        }
    }
}

__global__ void k_scan3() {
    int i = blockIdx.x * 1024 + threadIdx.x;
    if (i < NN) g_rowstart[i + 1] += g_bsum[blockIdx.x];
}

__global__ void k_prep() {
    int i = blockIdx.x * blockDim.x + threadIdx.x;
    if (i < NN) {
        g_fill[i] = g_rowstart[i];
        g_dinv[i] = rsqrtf((float)g_cnt[i] + 1.0f);  // self-loop adds 1
    }
}

__global__ void k_scatter(const int* __restrict__ ei, int E) {
    int e = blockIdx.x * blockDim.x + threadIdx.x;
    if (e < E) {
        int d = edst(ei, e, E);
        int pos = atomicAdd(&g_fill[d], 1);
        g_csr[pos] = esrc(ei, e);
    }
}

// ---------------- dense GEMM: g_t[n][M] = X[n][K] @ W[K][M] ----------------
// 64 rows per block, 256 threads, BK=32 K-tiles, register tile TM x 4.
// If Xext==nullptr, input is g_h (layers 2,3); output always g_t.
template <int K, int M>
__global__ void k_gemm(const float* __restrict__ Xext,
                       const float* __restrict__ W, int n) {
    constexpr int BK   = 32;
    constexpr int COLG = M / 4;        // column groups (float4 each)
    constexpr int ROWG = 256 / COLG;
    constexpr int TM   = 64 / ROWG;

    const float* __restrict__ X = Xext ? Xext : g_h;
    float* __restrict__ Y = g_t;

    __shared__ float xs[64][BK + 1];
    __shared__ float ws[BK][M];

    int t    = threadIdx.x;
    int colg = t % COLG;
    int rowg = t / COLG;
    int base = blockIdx.x * 64;

    float acc[TM][4];
#pragma unroll
    for (int i = 0; i < TM; i++)
#pragma unroll
        for (int j = 0; j < 4; j++) acc[i][j] = 0.f;

    for (int k0 = 0; k0 < K; k0 += BK) {
#pragma unroll
        for (int j = 0; j < 2; j++) {
            int idx = t + j * 256;
            int r   = idx >> 3;       // 0..63
            int kv  = idx & 7;        // 0..7
            float4 v = make_float4(0.f, 0.f, 0.f, 0.f);
            int row = base + r;
            if (row < n)
                v = *(const float4*)(X + (size_t)row * K + k0 + kv * 4);
            xs[r][kv * 4 + 0] = v.x;
            xs[r][kv * 4 + 1] = v.y;
            xs[r][kv * 4 + 2] = v.z;
            xs[r][kv * 4 + 3] = v.w;
        }
        constexpr int WV = (BK * M / 4) / 256;
#pragma unroll
        for (int j = 0; j < WV; j++) {
            int idx = t + j * 256;
            int kr  = idx / COLG;
            int mv  = idx % COLG;
            *(float4*)&ws[kr][mv * 4] =
                *(const float4*)(W + (size_t)(k0 + kr) * M + mv * 4);
        }
        __syncthreads();

#pragma unroll
        for (int k = 0; k < BK; k++) {
            float b0[4];
            *(float4*)b0 = *(float4*)&ws[k][colg * 4];
#pragma unroll
            for (int i = 0; i < TM; i++) {
                float a = xs[rowg * TM + i][k];
                acc[i][0] += a * b0[0];
                acc[i][1] += a * b0[1];
                acc[i][2] += a * b0[2];
                acc[i][3] += a * b0[3];
            }
        }
        __syncthreads();
    }

#pragma unroll
    for (int i = 0; i < TM; i++) {
        int row = base + rowg * TM + i;
        if (row < n)
            *(float4*)(Y + (size_t)row * M + colg * 4) =
                make_float4(acc[i][0], acc[i][1], acc[i][2], acc[i][3]);
    }
}

// ---------------- aggregation: warp per node, gather CSR rows ----------------
// g_h[d] = relu( dinv[d] * ( sum_{s in N(d)} g_t[s]*dinv[s] + g_t[d]*dinv[d] ) + b )
template <int M>
__global__ void k_agg(const float* __restrict__ bias) {
    constexpr int VEC = M / 32;
    const float* __restrict__ T = g_t;
    float* __restrict__ H = g_h;

    int gw   = (blockIdx.x * blockDim.x + threadIdx.x) >> 5;
    int lane = threadIdx.x & 31;
    if (gw >= NN) return;

    float dd = g_dinv[gw];
    int rs = g_rowstart[gw];
    int re = g_rowstart[gw + 1];

    float acc[VEC];
#pragma unroll
    for (int v = 0; v < VEC; v++) acc[v] = 0.f;

    for (int e = rs; e < re; e++) {
        int s = g_csr[e];
        float w = g_dinv[s];
        const float* row = T + (size_t)s * M + lane * VEC;
        if (VEC == 4) {
            float4 r4 = *(const float4*)row;
            acc[0] += r4.x * w; acc[1] += r4.y * w;
            acc[2] += r4.z * w; acc[3] += r4.w * w;
        } else if (VEC == 2) {
            float2 r2 = *(const float2*)row;
            acc[0] += r2.x * w; acc[1] += r2.y * w;
        } else {
            acc[0] += row[0] * w;
        }
    }
    const float* srow = T + (size_t)gw * M + lane * VEC;
#pragma unroll
    for (int v = 0; v < VEC; v++) acc[v] += srow[v] * dd;

#pragma unroll
    for (int v = 0; v < VEC; v++) {
        float o = acc[v] * dd + bias[lane * VEC + v];
        H[(size_t)gw * M + lane * VEC + v] = fmaxf(o, 0.f);
    }
}

// ---------------- edge scorer ----------------
__global__ void k_nodescore(const float* __restrict__ Wc) {
    int gw   = (blockIdx.x * blockDim.x + threadIdx.x) >> 5;
    int lane = threadIdx.x & 31;
    if (gw >= NN) return;
    float v = g_h[(size_t)gw * 32 + lane];
    float p = v * Wc[lane];
    float q = v * Wc[32 + lane];
#pragma unroll
    for (int o = 16; o; o >>= 1) {
        p += __shfl_xor_sync(0xFFFFFFFFu, p, o);
        q += __shfl_xor_sync(0xFFFFFFFFu, q, o);
    }
    if (lane == 0) { g_as[gw] = p; g_bs[gw] = q; }
}

__global__ void k_edgeout(const int* __restrict__ ei,
                          const float* __restrict__ bc,
                          float* __restrict__ out, int E) {
    int e = blockIdx.x * blockDim.x + threadIdx.x;
    if (e < E) out[e] = g_as[esrc(ei, e)] + g_bs[edst(ei, e, E)] + bc[0];
}

// ---------------- launch ----------------
extern "C" void kernel_launch(void* const* d_in, const int* in_sizes, int n_in,
                              void* d_out, int out_size) {
    const float* x   = (const float*)d_in[0];
    const int*   ei  = (const int*)d_in[1];
    const float* W1  = (const float*)d_in[2];
    const float* b1  = (const float*)d_in[3];
    const float* W2  = (const float*)d_in[4];
    const float* b2  = (const float*)d_in[5];
    const float* W3  = (const float*)d_in[6];
    const float* b3  = (const float*)d_in[7];
    const float* Wc  = (const float*)d_in[8];
    const float* bc  = (const float*)d_in[9];
    float*       out = (float*)d_out;

    int E = in_sizes[1] / 2;   // element count of edge_index = 2*E

    int nbN = (NN + 255) / 256;
    int nbE = (E + 255) / 256;
    int sb  = (NN + 1023) / 1024;
    int nbW = (NN * 32 + 255) / 256;   // warp-per-node kernels
    int nbG = (NN + 63) / 64;          // GEMM blocks

    // dtype probe + CSR build + normalization
    k_detect<<<1, 32>>>(ei);
    k_zero_cnt<<<nbN, 256>>>();
    k_hist<<<nbE, 256>>>(ei, E);
    k_scan1<<<sb, 1024>>>();
    k_scan2<<<1, 32>>>(sb);
    k_scan3<<<sb, 1024>>>();
    k_prep<<<nbN, 256>>>();
    k_scatter<<<nbE, 256>>>(ei, E);

    // layer 1: 128 -> 128
    k_gemm<128, 128><<<nbG, 256>>>(x, W1, NN);
    k_agg<128><<<nbW, 256>>>(b1);
    // layer 2: 128 -> 64
    k_gemm<128, 64><<<nbG, 256>>>(nullptr, W2, NN);
    k_agg<64><<<nbW, 256>>>(b2);
    // layer 3: 64 -> 32
    k_gemm<64, 32><<<nbG, 256>>>(nullptr, W3, NN);
    k_agg<32><<<nbW, 256>>>(b3);

    // edge scoring
    k_nodescore<<<nbW, 256>>>(Wc);
    k_edgeout<<<nbE, 256>>>(ei, bc, out, E);
}

// round 4
// speedup vs baseline: 1.0860x; 1.0860x over previous
#include <cuda_runtime.h>
#include <cuda_fp16.h>

#define NN   100000
#define MAXE 1600000

// ---------------- device scratch (static; no allocations) ----------------
__device__ __align__(16) float  g_t[(size_t)NN * 32];     // fp32 prescaled (layer 3)
__device__ __align__(16) __half2 g_tf16[(size_t)NN * 64]; // fp16 prescaled (layers 1,2)
__device__ __align__(16) float  g_h[(size_t)NN * 128];    // layer outputs (fp32)
__device__ float g_dinv[NN];
__device__ float g_as[NN];
__device__ float g_bs[NN];
__device__ int   g_cnt[NN];
__device__ int   g_rowstart[NN + 1];
__device__ int   g_fill[NN];
__device__ int   g_bsum[256];
__device__ int   g_csr[MAXE];   // src node per CSR slot (grouped by dst)
__device__ int   g_is64;        // 1 if edge_index buffer is int64-laid-out

// ---------------- edge index accessors (dtype-agnostic) ----------------
__device__ __forceinline__ int esrc(const int* __restrict__ ei, int e) {
    return g_is64 ? ei[2 * e] : ei[e];
}
__device__ __forceinline__ int edst(const int* __restrict__ ei, int e, int E) {
    return g_is64 ? ei[2 * (E + e)] : ei[E + e];
}

__global__ void k_detect(const int* __restrict__ ei) {
    int odd_nonzero = 0;
    for (int i = threadIdx.x; i < 256; i += 32)
        if (ei[2 * i + 1] != 0) odd_nonzero = 1;
    unsigned m = __ballot_sync(0xFFFFFFFFu, odd_nonzero);
    if (threadIdx.x == 0) g_is64 = (m == 0) ? 1 : 0;
}

// ---------------- graph preprocessing ----------------
__global__ void k_zero_cnt() {
    int i = blockIdx.x * blockDim.x + threadIdx.x;
    if (i < NN) g_cnt[i] = 0;
}

__global__ void k_hist(const int* __restrict__ ei, int E) {
    int e = blockIdx.x * blockDim.x + threadIdx.x;
    if (e < E) atomicAdd(&g_cnt[edst(ei, e, E)], 1);
}

__global__ void k_scan1() {
    __shared__ int sh[1024];
    int i = blockIdx.x * 1024 + threadIdx.x;
    int v = (i < NN) ? g_cnt[i] : 0;
    sh[threadIdx.x] = v;
    __syncthreads();
    for (int off = 1; off < 1024; off <<= 1) {
        int t = (threadIdx.x >= off) ? sh[threadIdx.x - off] : 0;
        __syncthreads();
        sh[threadIdx.x] += t;
        __syncthreads();
    }
    if (i < NN) g_rowstart[i + 1] = sh[threadIdx.x];
    if (threadIdx.x == 1023) g_bsum[blockIdx.x] = sh[1023];
    if (i == 0) g_rowstart[0] = 0;
}

__global__ void k_scan2(int nblocks) {
    if (threadIdx.x == 0 && blockIdx.x == 0) {
        int acc = 0;
        for (int b = 0; b < nblocks; b++) {
            int v = g_bsum[b];
            g_bsum[b] = acc;
            acc += v;
        }
    }
}

__global__ void k_scan3() {
    int i = blockIdx.x * 1024 + threadIdx.x;
    if (i < NN) g_rowstart[i + 1] += g_bsum[blockIdx.x];
}

__global__ void k_prep() {
    int i = blockIdx.x * blockDim.x + threadIdx.x;
    if (i < NN) {
        g_fill[i] = g_rowstart[i];
        g_dinv[i] = rsqrtf((float)g_cnt[i] + 1.0f);  // self-loop adds 1
    }
}

__global__ void k_scatter(const int* __restrict__ ei, int E) {
    int e = blockIdx.x * blockDim.x + threadIdx.x;
    if (e < E) {
        int d = edst(ei, e, E);
        int pos = atomicAdd(&g_fill[d], 1);
        g_csr[pos] = esrc(ei, e);
    }
}

// ---------------- dense GEMM: t[n][M] = (X[n][K] @ W[K][M]) * dinv[n] -------
// 64 rows/block, 256 threads, BK=32, register tile TM x 4.
// OUT16: store __half2 into g_tf16, else fp32 into g_t.
template <int K, int M, int OUT16>
__global__ void k_gemm(const float* __restrict__ Xext,
                       const float* __restrict__ W, int n) {
    constexpr int BK   = 32;
    constexpr int COLG = M / 4;
    constexpr int ROWG = 256 / COLG;
    constexpr int TM   = 64 / ROWG;

    const float* __restrict__ X = Xext ? Xext : g_h;

    __shared__ float xs[64][BK + 1];
    __shared__ float ws[BK][M];

    int t    = threadIdx.x;
    int colg = t % COLG;
    int rowg = t / COLG;
    int base = blockIdx.x * 64;

    float acc[TM][4];
#pragma unroll
    for (int i = 0; i < TM; i++)
#pragma unroll
        for (int j = 0; j < 4; j++) acc[i][j] = 0.f;

    for (int k0 = 0; k0 < K; k0 += BK) {
#pragma unroll
        for (int j = 0; j < 2; j++) {
            int idx = t + j * 256;
            int r   = idx >> 3;
            int kv  = idx & 7;
            float4 v = make_float4(0.f, 0.f, 0.f, 0.f);
            int row = base + r;
            if (row < n)
                v = *(const float4*)(X + (size_t)row * K + k0 + kv * 4);
            xs[r][kv * 4 + 0] = v.x;
            xs[r][kv * 4 + 1] = v.y;
            xs[r][kv * 4 + 2] = v.z;
            xs[r][kv * 4 + 3] = v.w;
        }
        constexpr int WV = (BK * M / 4) / 256;
#pragma unroll
        for (int j = 0; j < WV; j++) {
            int idx = t + j * 256;
            int kr  = idx / COLG;
            int mv  = idx % COLG;
            *(float4*)&ws[kr][mv * 4] =
                *(const float4*)(W + (size_t)(k0 + kr) * M + mv * 4);
        }
        __syncthreads();

#pragma unroll
        for (int k = 0; k < BK; k++) {
            float b0[4];
            *(float4*)b0 = *(float4*)&ws[k][colg * 4];
#pragma unroll
            for (int i = 0; i < TM; i++) {
                float a = xs[rowg * TM + i][k];
                acc[i][0] += a * b0[0];
                acc[i][1] += a * b0[1];
                acc[i][2] += a * b0[2];
                acc[i][3] += a * b0[3];
            }
        }
        __syncthreads();
    }

#pragma unroll
    for (int i = 0; i < TM; i++) {
        int row = base + rowg * TM + i;
        if (row < n) {
            float s = g_dinv[row];
            if (OUT16) {
                __half2 p0 = __floats2half2_rn(acc[i][0] * s, acc[i][1] * s);
                __half2 p1 = __floats2half2_rn(acc[i][2] * s, acc[i][3] * s);
                float2 w2;
                *(__half2*)&w2.x = p0;
                *(__half2*)&w2.y = p1;
                *(float2*)(g_tf16 + (size_t)row * (M / 2) + colg * 2) = w2;
            } else {
                *(float4*)(g_t + (size_t)row * M + colg * 4) =
                    make_float4(acc[i][0] * s, acc[i][1] * s,
                                acc[i][2] * s, acc[i][3] * s);
            }
        }
    }
}

// ---------- aggregation over fp16 prescaled rows (layers 1,2) ----------
// g_h[d] = relu( dinv[d] * ( sum_{s in N(d)} t~[s] + t~[d] ) + bias )
template <int M>
__global__ void k_agg_h(const float* __restrict__ bias) {
    constexpr int V2 = M / 64;   // half2 per lane: 2 (M=128) or 1 (M=64)
    int gw   = (blockIdx.x * blockDim.x + threadIdx.x) >> 5;
    int lane = threadIdx.x & 31;
    if (gw >= NN) return;

    float dd = g_dinv[gw];
    int rs = g_rowstart[gw];
    int re = g_rowstart[gw + 1];

    float acc[2 * V2];
#pragma unroll
    for (int v = 0; v < 2 * V2; v++) acc[v] = 0.f;

    for (int e = rs; e < re; e++) {
        int s = g_csr[e];
        const __half2* row = g_tf16 + (size_t)s * (M / 2) + lane * V2;
        if (V2 == 2) {
            float2 raw = *(const float2*)row;
            float2 f0 = __half22float2(*(__half2*)&raw.x);
            float2 f1 = __half22float2(*(__half2*)&raw.y);
            acc[0] += f0.x; acc[1] += f0.y;
            acc[2] += f1.x; acc[3] += f1.y;
        } else {
            float2 f0 = __half22float2(row[0]);
            acc[0] += f0.x; acc[1] += f0.y;
        }
    }
    // self loop
    {
        const __half2* row = g_tf16 + (size_t)gw * (M / 2) + lane * V2;
#pragma unroll
        for (int v = 0; v < V2; v++) {
            float2 f = __half22float2(row[v]);
            acc[2 * v] += f.x; acc[2 * v + 1] += f.y;
        }
    }
#pragma unroll
    for (int v = 0; v < 2 * V2; v++) {
        float o = acc[v] * dd + bias[lane * 2 * V2 + v];
        g_h[(size_t)gw * M + lane * 2 * V2 + v] = fmaxf(o, 0.f);
    }
}

// ---------- aggregation over fp32 prescaled rows (layer 3, M=32) ----------
__global__ void k_agg_f32(const float* __restrict__ bias) {
    int gw   = (blockIdx.x * blockDim.x + threadIdx.x) >> 5;
    int lane = threadIdx.x & 31;
    if (gw >= NN) return;

    float dd = g_dinv[gw];
    int rs = g_rowstart[gw];
    int re = g_rowstart[gw + 1];

    float acc = 0.f;
    for (int e = rs; e < re; e++) {
        int s = g_csr[e];
        acc += g_t[(size_t)s * 32 + lane];
    }
    acc += g_t[(size_t)gw * 32 + lane];

    float o = acc * dd + bias[lane];
    g_h[(size_t)gw * 32 + lane] = fmaxf(o, 0.f);
}

// ---------------- edge scorer ----------------
__global__ void k_nodescore(const float* __restrict__ Wc) {
    int gw   = (blockIdx.x * blockDim.x + threadIdx.x) >> 5;
    int lane = threadIdx.x & 31;
    if (gw >= NN) return;
    float v = g_h[(size_t)gw * 32 + lane];
    float p = v * Wc[lane];
    float q = v * Wc[32 + lane];
#pragma unroll
    for (int o = 16; o; o >>= 1) {
        p += __shfl_xor_sync(0xFFFFFFFFu, p, o);
        q += __shfl_xor_sync(0xFFFFFFFFu, q, o);
    }
    if (lane == 0) { g_as[gw] = p; g_bs[gw] = q; }
}

__global__ void k_edgeout(const int* __restrict__ ei,
                          const float* __restrict__ bc,
                          float* __restrict__ out, int E) {
    int e = blockIdx.x * blockDim.x + threadIdx.x;
    if (e < E) out[e] = g_as[esrc(ei, e)] + g_bs[edst(ei, e, E)] + bc[0];
}

// ---------------- launch ----------------
extern "C" void kernel_launch(void* const* d_in, const int* in_sizes, int n_in,
                              void* d_out, int out_size) {
    const float* x   = (const float*)d_in[0];
    const int*   ei  = (const int*)d_in[1];
    const float* W1  = (const float*)d_in[2];
    const float* b1  = (const float*)d_in[3];
    const float* W2  = (const float*)d_in[4];
    const float* b2  = (const float*)d_in[5];
    const float* W3  = (const float*)d_in[6];
    const float* b3  = (const float*)d_in[7];
    const float* Wc  = (const float*)d_in[8];
    const float* bc  = (const float*)d_in[9];
    float*       out = (float*)d_out;

    int E = in_sizes[1] / 2;

    int nbN = (NN + 255) / 256;
    int nbE = (E + 255) / 256;
    int sb  = (NN + 1023) / 1024;
    int nbW = (NN * 32 + 255) / 256;   // warp-per-node kernels
    int nbG = (NN + 63) / 64;          // GEMM blocks

    // dtype probe + CSR build + normalization
    k_detect<<<1, 32>>>(ei);
    k_zero_cnt<<<nbN, 256>>>();
    k_hist<<<nbE, 256>>>(ei, E);
    k_scan1<<<sb, 1024>>>();
    k_scan2<<<1, 32>>>(sb);
    k_scan3<<<sb, 1024>>>();
    k_prep<<<nbN, 256>>>();
    k_scatter<<<nbE, 256>>>(ei, E);

    // layer 1: 128 -> 128 (fp16 prescaled gather)
    k_gemm<128, 128, 1><<<nbG, 256>>>(x, W1, NN);
    k_agg_h<128><<<nbW, 256>>>(b1);
    // layer 2: 128 -> 64 (fp16 prescaled gather)
    k_gemm<128, 64, 1><<<nbG, 256>>>(nullptr, W2, NN);
    k_agg_h<64><<<nbW, 256>>>(b2);
    // layer 3: 64 -> 32 (fp32 prescaled gather)
    k_gemm<64, 32, 0><<<nbG, 256>>>(nullptr, W3, NN);
    k_agg_f32<<<nbW, 256>>>(b3);

    // edge scoring
    k_nodescore<<<nbW, 256>>>(Wc);
    k_edgeout<<<nbE, 256>>>(ei, bc, out, E);
}

// round 6
// speedup vs baseline: 1.2239x; 1.1269x over previous
#include <cuda_runtime.h>
#include <cuda_fp16.h>
#include <stdint.h>

#define NN   100000
#define MAXE 1600000

// ---------------- device scratch (static; no allocations) ----------------
__device__ __align__(16) float   g_t[(size_t)NN * 32];     // fp32 prescaled (layer 3)
__device__ __align__(16) __half2 g_tf16[(size_t)NN * 64];  // fp16 prescaled (layers 1,2)
__device__ __align__(16) float   g_h[(size_t)NN * 128];    // layer outputs (fp32)
__device__ float g_dinv[NN];
__device__ float g_as[NN];
__device__ float g_bs[NN];
__device__ int   g_cnt[NN];
__device__ int   g_rowstart[NN + 1];
__device__ int   g_fill[NN];
__device__ int   g_bsum[256];
__device__ int   g_csr[MAXE];
__device__ int   g_is64;

// ---------------- edge index accessors (dtype-agnostic) ----------------
__device__ __forceinline__ int esrc(const int* __restrict__ ei, int e) {
    return g_is64 ? ei[2 * e] : ei[e];
}
__device__ __forceinline__ int edst(const int* __restrict__ ei, int e, int E) {
    return g_is64 ? ei[2 * (E + e)] : ei[E + e];
}

__global__ void k_detect(const int* __restrict__ ei) {
    int odd_nonzero = 0;
    for (int i = threadIdx.x; i < 256; i += 32)
        if (ei[2 * i + 1] != 0) odd_nonzero = 1;
    unsigned m = __ballot_sync(0xFFFFFFFFu, odd_nonzero);
    if (threadIdx.x == 0) g_is64 = (m == 0) ? 1 : 0;
}

// ---------------- graph preprocessing ----------------
__global__ void k_zero_cnt() {
    int i = blockIdx.x * blockDim.x + threadIdx.x;
    if (i < NN) g_cnt[i] = 0;
}

__global__ void k_hist(const int* __restrict__ ei, int E) {
    int e = blockIdx.x * blockDim.x + threadIdx.x;
    if (e < E) atomicAdd(&g_cnt[edst(ei, e, E)], 1);
}

__global__ void k_scan1() {
    __shared__ int sh[1024];
    int i = blockIdx.x * 1024 + threadIdx.x;
    int v = (i < NN) ? g_cnt[i] : 0;
    sh[threadIdx.x] = v;
    __syncthreads();
    for (int off = 1; off < 1024; off <<= 1) {
        int t = (threadIdx.x >= off) ? sh[threadIdx.x - off] : 0;
        __syncthreads();
        sh[threadIdx.x] += t;
        __syncthreads();
    }
    if (i < NN) g_rowstart[i + 1] = sh[threadIdx.x];
    if (threadIdx.x == 1023) g_bsum[blockIdx.x] = sh[1023];
    if (i == 0) g_rowstart[0] = 0;
}

__global__ void k_scan2(int nblocks) {
    if (threadIdx.x == 0 && blockIdx.x == 0) {
        int acc = 0;
        for (int b = 0; b < nblocks; b++) {
            int v = g_bsum[b];
            g_bsum[b] = acc;
            acc += v;
        }
    }
}

__global__ void k_scan3() {
    int i = blockIdx.x * 1024 + threadIdx.x;
    if (i < NN) g_rowstart[i + 1] += g_bsum[blockIdx.x];
}

__global__ void k_prep() {
    int i = blockIdx.x * blockDim.x + threadIdx.x;
    if (i < NN) {
        g_fill[i] = g_rowstart[i];
        g_dinv[i] = rsqrtf((float)g_cnt[i] + 1.0f);
    }
}

__global__ void k_scatter(const int* __restrict__ ei, int E) {
    int e = blockIdx.x * blockDim.x + threadIdx.x;
    if (e < E) {
        int d = edst(ei, e, E);
        int pos = atomicAdd(&g_fill[d], 1);
        g_csr[pos] = esrc(ei, e);
    }
}

// ---- split-fp16 tensor GEMM (3-term, ~fp32 accurate): t~=(X@W)*dinv, fp16 out ----
// Block tile: 128 rows x M cols, 256 threads (8 warps). K staged by BK=32.
// A = A_hi + A_lo, W = W_hi + W_lo; acc += Ah*Wh + Ah*Wl + Al*Wh (fp32 acc).
template <int K, int M>
__global__ void k_gemm_mma(const float* __restrict__ Xext,
                           const float* __restrict__ W, int n) {
    constexpr int BK  = 32;
    constexpr int STG = K / BK;
    constexpr int AP  = BK + 8;              // half pitch
    constexpr int WC  = (M >= 128) ? 2 : 1;  // warp cols
    constexpr int WR  = 8 / WC;              // warp rows
    constexpr int WROWS = 128 / WR;          // 32 or 16
    constexpr int WCOLS = M / WC;            // 64
    constexpr int MT  = WROWS / 16;          // 2 or 1
    constexpr int NT  = WCOLS / 8;           // 8

    __shared__ __align__(16) __half Ah[128 * AP];
    __shared__ __align__(16) __half Al[128 * AP];
    __shared__ __align__(16) __half Bh[M * AP];
    __shared__ __align__(16) __half Bl[M * AP];

    const float* __restrict__ X = Xext ? Xext : g_h;
    int t    = threadIdx.x;
    int warp = t >> 5, lane = t & 31;
    int g    = lane >> 2, tg = lane & 3;
    int wm   = (warp % WR) * WROWS;
    int wn   = (warp / WR) * WCOLS;
    int base = blockIdx.x * 128;

    float acc[MT][NT][4];
#pragma unroll
    for (int mt = 0; mt < MT; mt++)
#pragma unroll
        for (int nt = 0; nt < NT; nt++)
#pragma unroll
            for (int j = 0; j < 4; j++) acc[mt][nt][j] = 0.f;

    for (int s = 0; s < STG; s++) {
        int k0 = s * BK;
        // A tile: 128 x 32 fp32 (1024 float4, 4/thread) -> hi/lo fp16
#pragma unroll
        for (int j = 0; j < 4; j++) {
            int idx = t + j * 256;
            int r = idx >> 3, c4 = idx & 7;
            float4 v = make_float4(0.f, 0.f, 0.f, 0.f);
            if (base + r < n)
                v = *(const float4*)(X + (size_t)(base + r) * K + k0 + c4 * 4);
            __half hx = __float2half_rn(v.x), hy = __float2half_rn(v.y);
            __half hz = __float2half_rn(v.z), hw = __float2half_rn(v.w);
            __half2 h0, h1, l0, l1;
            h0 = __halves2half2(hx, hy);
            h1 = __halves2half2(hz, hw);
            l0 = __floats2half2_rn(v.x - __half2float(hx), v.y - __half2float(hy));
            l1 = __floats2half2_rn(v.z - __half2float(hz), v.w - __half2float(hw));
            uint2 uh, ul;
            uh.x = *(unsigned*)&h0; uh.y = *(unsigned*)&h1;
            ul.x = *(unsigned*)&l0; ul.y = *(unsigned*)&l1;
            *(uint2*)&Ah[r * AP + c4 * 4] = uh;
            *(uint2*)&Al[r * AP + c4 * 4] = ul;
        }
        // W tile transposed: B[m][k] = W[k0+k][m], hi/lo
        constexpr int WE = (BK * M) / 256;
#pragma unroll
        for (int j = 0; j < WE; j++) {
            int idx = t + j * 256;
            int k = idx / M, m = idx % M;
            float w = W[(size_t)(k0 + k) * M + m];
            __half wh = __float2half_rn(w);
            Bh[m * AP + k] = wh;
            Bl[m * AP + k] = __float2half_rn(w - __half2float(wh));
        }
        __syncthreads();

#pragma unroll
        for (int kk = 0; kk < BK; kk += 16) {
            unsigned ah[MT][4], al[MT][4], bh[NT][2], bl[NT][2];
#pragma unroll
            for (int mt = 0; mt < MT; mt++) {
                int off = (wm + mt * 16 + g) * AP + kk + tg * 2;
                ah[mt][0] = *(const unsigned*)&Ah[off];
                ah[mt][1] = *(const unsigned*)&Ah[off + 8 * AP];
                ah[mt][2] = *(const unsigned*)&Ah[off + 8];
                ah[mt][3] = *(const unsigned*)&Ah[off + 8 * AP + 8];
                al[mt][0] = *(const unsigned*)&Al[off];
                al[mt][1] = *(const unsigned*)&Al[off + 8 * AP];
                al[mt][2] = *(const unsigned*)&Al[off + 8];
                al[mt][3] = *(const unsigned*)&Al[off + 8 * AP + 8];
            }
#pragma unroll
            for (int nt = 0; nt < NT; nt++) {
                int off = (wn + nt * 8 + g) * AP + kk + tg * 2;
                bh[nt][0] = *(const unsigned*)&Bh[off];
                bh[nt][1] = *(const unsigned*)&Bh[off + 8];
                bl[nt][0] = *(const unsigned*)&Bl[off];
                bl[nt][1] = *(const unsigned*)&Bl[off + 8];
            }
#define MMA(AC, A0, A1, A2, A3, B0, B1)                                       \
    asm volatile(                                                             \
        "mma.sync.aligned.m16n8k16.row.col.f32.f16.f16.f32 "                  \
        "{%0,%1,%2,%3},{%4,%5,%6,%7},{%8,%9},{%0,%1,%2,%3};"                  \
        : "+f"(AC[0]), "+f"(AC[1]), "+f"(AC[2]), "+f"(AC[3])                  \
        : "r"(A0), "r"(A1), "r"(A2), "r"(A3), "r"(B0), "r"(B1))
#pragma unroll
            for (int mt = 0; mt < MT; mt++)
#pragma unroll
                for (int nt = 0; nt < NT; nt++) {
                    MMA(acc[mt][nt], ah[mt][0], ah[mt][1], ah[mt][2], ah[mt][3],
                        bh[nt][0], bh[nt][1]);
                    MMA(acc[mt][nt], ah[mt][0], ah[mt][1], ah[mt][2], ah[mt][3],
                        bl[nt][0], bl[nt][1]);
                    MMA(acc[mt][nt], al[mt][0], al[mt][1], al[mt][2], al[mt][3],
                        bh[nt][0], bh[nt][1]);
                }
#undef MMA
        }
        __syncthreads();
    }

    // epilogue: scale by dinv, pack fp16
#pragma unroll
    for (int mt = 0; mt < MT; mt++) {
        int r0 = base + wm + mt * 16 + g;
        int r1 = r0 + 8;
        float s0 = (r0 < n) ? g_dinv[r0] : 0.f;
        float s1 = (r1 < n) ? g_dinv[r1] : 0.f;
#pragma unroll
        for (int nt = 0; nt < NT; nt++) {
            int c = wn + nt * 8 + tg * 2;
            if (r0 < n)
                g_tf16[(size_t)r0 * (M / 2) + (c >> 1)] =
                    __floats2half2_rn(acc[mt][nt][0] * s0, acc[mt][nt][1] * s0);
            if (r1 < n)
                g_tf16[(size_t)r1 * (M / 2) + (c >> 1)] =
                    __floats2half2_rn(acc[mt][nt][2] * s1, acc[mt][nt][3] * s1);
        }
    }
}

// ------- fp32 FFMA GEMM (layer 3 only): g_t = (g_h @ W) * dinv -------
template <int K, int M>
__global__ void k_gemm_f32(const float* __restrict__ W, int n) {
    constexpr int BK   = 32;
    constexpr int COLG = M / 4;
    constexpr int ROWG = 256 / COLG;
    constexpr int TM   = 64 / ROWG;

    const float* __restrict__ X = g_h;

    __shared__ float xs[64][BK + 1];
    __shared__ float ws[BK][M];

    int t    = threadIdx.x;
    int colg = t % COLG;
    int rowg = t / COLG;
    int base = blockIdx.x * 64;

    float acc[TM][4];
#pragma unroll
    for (int i = 0; i < TM; i++)
#pragma unroll
        for (int j = 0; j < 4; j++) acc[i][j] = 0.f;

    for (int k0 = 0; k0 < K; k0 += BK) {
#pragma unroll
        for (int j = 0; j < 2; j++) {
            int idx = t + j * 256;
            int r   = idx >> 3;
            int kv  = idx & 7;
            float4 v = make_float4(0.f, 0.f, 0.f, 0.f);
            int row = base + r;
            if (row < n)
                v = *(const float4*)(X + (size_t)row * K + k0 + kv * 4);
            xs[r][kv * 4 + 0] = v.x;
            xs[r][kv * 4 + 1] = v.y;
            xs[r][kv * 4 + 2] = v.z;
            xs[r][kv * 4 + 3] = v.w;
        }
        constexpr int WV = (BK * M / 4) / 256;
#pragma unroll
        for (int j = 0; j < WV; j++) {
            int idx = t + j * 256;
            int kr  = idx / COLG;
            int mv  = idx % COLG;
            *(float4*)&ws[kr][mv * 4] =
                *(const float4*)(W + (size_t)(k0 + kr) * M + mv * 4);
        }
        __syncthreads();

#pragma unroll
        for (int k = 0; k < BK; k++) {
            float b0[4];
            *(float4*)b0 = *(float4*)&ws[k][colg * 4];
#pragma unroll
            for (int i = 0; i < TM; i++) {
                float a = xs[rowg * TM + i][k];
                acc[i][0] += a * b0[0];
                acc[i][1] += a * b0[1];
                acc[i][2] += a * b0[2];
                acc[i][3] += a * b0[3];
            }
        }
        __syncthreads();
    }

#pragma unroll
    for (int i = 0; i < TM; i++) {
        int row = base + rowg * TM + i;
        if (row < n) {
            float s = g_dinv[row];
            *(float4*)(g_t + (size_t)row * M + colg * 4) =
                make_float4(acc[i][0] * s, acc[i][1] * s,
                            acc[i][2] * s, acc[i][3] * s);
        }
    }
}

// ---------- aggregation over fp16 prescaled rows (layers 1,2) ----------
template <int M>
__global__ void k_agg_h(const float* __restrict__ bias) {
    constexpr int V2 = M / 64;
    int gw   = (blockIdx.x * blockDim.x + threadIdx.x) >> 5;
    int lane = threadIdx.x & 31;
    if (gw >= NN) return;

    float dd = g_dinv[gw];
    int rs = g_rowstart[gw];
    int re = g_rowstart[gw + 1];

    float acc[2 * V2];
#pragma unroll
    for (int v = 0; v < 2 * V2; v++) acc[v] = 0.f;

    for (int e = rs; e < re; e++) {
        int s = g_csr[e];
        const __half2* row = g_tf16 + (size_t)s * (M / 2) + lane * V2;
        if (V2 == 2) {
            float2 raw = *(const float2*)row;
            float2 f0 = __half22float2(*(__half2*)&raw.x);
            float2 f1 = __half22float2(*(__half2*)&raw.y);
            acc[0] += f0.x; acc[1] += f0.y;
            acc[2] += f1.x; acc[3] += f1.y;
        } else {
            float2 f0 = __half22float2(row[0]);
            acc[0] += f0.x; acc[1] += f0.y;
        }
    }
    {
        const __half2* row = g_tf16 + (size_t)gw * (M / 2) + lane * V2;
#pragma unroll
        for (int v = 0; v < V2; v++) {
            float2 f = __half22float2(row[v]);
            acc[2 * v] += f.x; acc[2 * v + 1] += f.y;
        }
    }
#pragma unroll
    for (int v = 0; v < 2 * V2; v++) {
        float o = acc[v] * dd + bias[lane * 2 * V2 + v];
        g_h[(size_t)gw * M + lane * 2 * V2 + v] = fmaxf(o, 0.f);
    }
}

// ---- layer-3 aggregation fused with node scoring (h3 never materialized) ----
__global__ void k_agg3_score(const float* __restrict__ bias,
                             const float* __restrict__ Wc) {
    int gw   = (blockIdx.x * blockDim.x + threadIdx.x) >> 5;
    int lane = threadIdx.x & 31;
    if (gw >= NN) return;

    float dd = g_dinv[gw];
    int rs = g_rowstart[gw];
    int re = g_rowstart[gw + 1];

    float acc = 0.f;
    for (int e = rs; e < re; e++)
        acc += g_t[(size_t)g_csr[e] * 32 + lane];
    acc += g_t[(size_t)gw * 32 + lane];

    float o = fmaxf(acc * dd + bias[lane], 0.f);
    float p = o * Wc[lane];
    float q = o * Wc[32 + lane];
#pragma unroll
    for (int off = 16; off; off >>= 1) {
        p += __shfl_xor_sync(0xFFFFFFFFu, p, off);
        q += __shfl_xor_sync(0xFFFFFFFFu, q, off);
    }
    if (lane == 0) { g_as[gw] = p; g_bs[gw] = q; }
}

__global__ void k_edgeout(const int* __restrict__ ei,
                          const float* __restrict__ bc,
                          float* __restrict__ out, int E) {
    int e = blockIdx.x * blockDim.x + threadIdx.x;
    if (e < E) out[e] = g_as[esrc(ei, e)] + g_bs[edst(ei, e, E)] + bc[0];
}

// ---------------- launch ----------------
extern "C" void kernel_launch(void* const* d_in, const int* in_sizes, int n_in,
                              void* d_out, int out_size) {
    const float* x   = (const float*)d_in[0];
    const int*   ei  = (const int*)d_in[1];
    const float* W1  = (const float*)d_in[2];
    const float* b1  = (const float*)d_in[3];
    const float* W2  = (const float*)d_in[4];
    const float* b2  = (const float*)d_in[5];
    const float* W3  = (const float*)d_in[6];
    const float* b3  = (const float*)d_in[7];
    const float* Wc  = (const float*)d_in[8];
    const float* bc  = (const float*)d_in[9];
    float*       out = (float*)d_out;

    int E = in_sizes[1] / 2;

    int nbN = (NN + 255) / 256;
    int nbE = (E + 255) / 256;
    int sb  = (NN + 1023) / 1024;
    int nbW = (NN * 32 + 255) / 256;    // warp-per-node kernels
    int nbM = (NN + 127) / 128;         // mma GEMM blocks
    int nbG = (NN + 63) / 64;           // f32 GEMM blocks

    // dtype probe + CSR build + normalization
    k_detect<<<1, 32>>>(ei);
    k_zero_cnt<<<nbN, 256>>>();
    k_hist<<<nbE, 256>>>(ei, E);
    k_scan1<<<sb, 1024>>>();
    k_scan2<<<1, 32>>>(sb);
    k_scan3<<<sb, 1024>>>();
    k_prep<<<nbN, 256>>>();
    k_scatter<<<nbE, 256>>>(ei, E);

    // layer 1: 128 -> 128 (split-fp16 tensor GEMM, fp16 prescaled gather)
    k_gemm_mma<128, 128><<<nbM, 256>>>(x, W1, NN);
    k_agg_h<128><<<nbW, 256>>>(b1);
    // layer 2: 128 -> 64
    k_gemm_mma<128, 64><<<nbM, 256>>>(nullptr, W2, NN);
    k_agg_h<64><<<nbW, 256>>>(b2);
    // layer 3: 64 -> 32 (fp32 FFMA GEMM, fp32 gather + fused scoring)
    k_gemm_f32<64, 32><<<nbG, 256>>>(W3, NN);
    k_agg3_score<<<nbW, 256>>>(b3, Wc);

    // edge scoring
    k_edgeout<<<nbE, 256>>>(ei, bc, out, E);
}